// round 1
// baseline (speedup 1.0000x reference)
#include <cuda_runtime.h>
#include <math.h>

#define G        512
#define S        32
#define PTS      8
#define SEGS_PER (PTS - 1)           // 7
#define NSEG     (S * SEGS_PER)      // 224
#define TILE     16

struct Seg {
    float vx, vy, ex, ey, invd2, scale, r, pad;
};

__device__ Seg g_segs[NSEG];

// ---------------------------------------------------------------------------
// Precompute per-segment constants: clamped pixel coords, direction, 1/(d2+eps),
// 1/(4t^2) (scaled-squared-distance factor), and cull radius r = 2t.
// ---------------------------------------------------------------------------
__global__ void prep_kernel(const float* __restrict__ strokes,
                            const float* __restrict__ thick) {
    int idx = threadIdx.x;
    if (idx >= NSEG) return;
    int s = idx / SEGS_PER;
    int k = idx % SEGS_PER;

    const float* p0 = strokes + (s * PTS + k) * 2;
    const float* p1 = strokes + (s * PTS + k + 1) * 2;

    float vx = fminf(fmaxf(p0[0], 0.0f), 1.0f) * (float)G;
    float vy = fminf(fmaxf(p0[1], 0.0f), 1.0f) * (float)G;
    float wx = fminf(fmaxf(p1[0], 0.0f), 1.0f) * (float)G;
    float wy = fminf(fmaxf(p1[1], 0.0f), 1.0f) * (float)G;

    float ex = wx - vx;
    float ey = wy - vy;
    float d2 = ex * ex + ey * ey;

    float t = fmaxf(thick[s] * 2.0f + 0.5f, 0.5f);

    Seg sg;
    sg.vx    = vx;
    sg.vy    = vy;
    sg.ex    = ex;
    sg.ey    = ey;
    sg.invd2 = 1.0f / (d2 + 1e-5f);
    sg.scale = 1.0f / (4.0f * t * t);   // darkness^2 = dq * scale
    sg.r     = 2.0f * t;                // influence radius (darkness >= 1 beyond)
    sg.pad   = 0.0f;
    g_segs[idx] = sg;
}

// ---------------------------------------------------------------------------
// Render: one 16x16 block per tile.
// Phase 1: cull 224 segments vs tile center (conservative), compact to SMEM.
// Phase 2: per-pixel min over surviving segments of scaled squared distance.
// ---------------------------------------------------------------------------
__global__ void __launch_bounds__(TILE * TILE)
render_kernel(float* __restrict__ out) {
    __shared__ float s_vx[NSEG], s_vy[NSEG], s_ex[NSEG], s_ey[NSEG];
    __shared__ float s_id2[NSEG], s_sc[NSEG];
    __shared__ int   s_n;

    const int tid = threadIdx.y * TILE + threadIdx.x;
    if (tid == 0) s_n = 0;
    __syncthreads();

    const int ti = blockIdx.y * TILE;   // coord-0 (row, out stride G)
    const int tj = blockIdx.x * TILE;   // coord-1 (contiguous)

    // Tile center & max pixel radius (half-diag of 15x15 span) + safety margin
    const float cx = (float)ti + (TILE - 1) * 0.5f;
    const float cy = (float)tj + (TILE - 1) * 0.5f;
    const float RMAX = (TILE - 1) * 0.5f * 1.41421356f + 1.0f;

    if (tid < NSEG) {
        Seg sg = g_segs[tid];
        float dx  = cx - sg.vx;
        float dy  = cy - sg.vy;
        float dot = dx * sg.ex + dy * sg.ey;
        float fr  = __saturatef(dot * sg.invd2);
        float ddx = fmaf(-fr, sg.ex, dx);
        float ddy = fmaf(-fr, sg.ey, dy);
        float dq  = ddx * ddx + ddy * ddy;
        float thr = sg.r + RMAX;        // keep if dist(center,seg) <= 2t + rmax
        if (dq <= thr * thr) {
            int p = atomicAdd(&s_n, 1);
            s_vx[p]  = sg.vx;
            s_vy[p]  = sg.vy;
            s_ex[p]  = sg.ex;
            s_ey[p]  = sg.ey;
            s_id2[p] = sg.invd2;
            s_sc[p]  = sg.scale;
        }
    }
    __syncthreads();

    const int n = s_n;
    const float px = (float)(ti + threadIdx.y);
    const float py = (float)(tj + threadIdx.x);

    float m = 1e30f;
    for (int q = 0; q < n; q++) {
        float vx  = s_vx[q], vy = s_vy[q];
        float ex  = s_ex[q], ey = s_ey[q];
        float dx  = px - vx;
        float dy  = py - vy;
        float dot = dx * ex + dy * ey;
        float fr  = __saturatef(dot * s_id2[q]);
        float ddx = fmaf(-fr, ex, dx);
        float ddy = fmaf(-fr, ey, dy);
        float dq  = fmaf(ddx, ddx, ddy * ddy);
        m = fminf(m, dq * s_sc[q]);
    }

    out[(ti + threadIdx.y) * G + (tj + threadIdx.x)] = fminf(sqrtf(m), 1.0f);
}

extern "C" void kernel_launch(void* const* d_in, const int* in_sizes, int n_in,
                              void* d_out, int out_size) {
    // metadata order: strokes [32,8,2] f32 (512 elems), thicknesses [32] f32.
    const float* strokes = (const float*)d_in[0];
    const float* thick   = (const float*)d_in[1];
    if (n_in >= 2 && in_sizes[0] == S && in_sizes[1] == S * PTS * 2) {
        // defensive: swapped metadata order
        strokes = (const float*)d_in[1];
        thick   = (const float*)d_in[0];
    }
    float* out = (float*)d_out;

    prep_kernel<<<1, 256>>>(strokes, thick);
    dim3 block(TILE, TILE);
    dim3 grid(G / TILE, G / TILE);
    render_kernel<<<grid, block>>>(out);
}

// round 2
// speedup vs baseline: 1.6411x; 1.6411x over previous
#include <cuda_runtime.h>
#include <math.h>

#define G        512
#define S        32
#define PTS      8
#define SEGS_PER (PTS - 1)           // 7
#define NSEG     (S * SEGS_PER)      // 224
#define TILE     16

// ---------------------------------------------------------------------------
// Single fused kernel: one 16x16 block per tile.
// Phase 1 (threads 0..223): compute per-segment constants directly from the
//   raw inputs (L2-cached), cull against the tile center, compact survivors
//   into SMEM (float4 + float2 layout for vector LDS in the hot loop).
// Phase 2: per-pixel min over survivors of scaled squared distance; one
//   sqrt at the end (min is monotone under sqrt).
// ---------------------------------------------------------------------------
__global__ void __launch_bounds__(TILE * TILE)
render_kernel(const float* __restrict__ strokes,
              const float* __restrict__ thick,
              float* __restrict__ out) {
    __shared__ float4 s_a[NSEG];     // vx, vy, ex, ey
    __shared__ float2 s_b[NSEG];     // invd2, scale
    __shared__ int    s_n;

    const int tid = threadIdx.y * TILE + threadIdx.x;
    if (tid == 0) s_n = 0;
    __syncthreads();

    const int ti = blockIdx.y * TILE;   // coord-0 (row, out stride G)
    const int tj = blockIdx.x * TILE;   // coord-1 (contiguous)

    // Tile center & conservative cull radius: half-diag of 15x15 span + margin
    const float cx   = (float)ti + (TILE - 1) * 0.5f;
    const float cy   = (float)tj + (TILE - 1) * 0.5f;
    const float RMAX = (TILE - 1) * 0.5f * 1.41421356f + 1.0f;

    if (tid < NSEG) {
        const int s = tid / SEGS_PER;
        const int k = tid % SEGS_PER;

        const float* p0 = strokes + (s * PTS + k) * 2;

        float vx = fminf(fmaxf(p0[0], 0.0f), 1.0f) * (float)G;
        float vy = fminf(fmaxf(p0[1], 0.0f), 1.0f) * (float)G;
        float wx = fminf(fmaxf(p0[2], 0.0f), 1.0f) * (float)G;
        float wy = fminf(fmaxf(p0[3], 0.0f), 1.0f) * (float)G;

        float ex = wx - vx;
        float ey = wy - vy;
        float d2 = ex * ex + ey * ey;
        float invd2 = 1.0f / (d2 + 1e-5f);

        float t = fmaxf(thick[s] * 2.0f + 0.5f, 0.5f);

        // cull: distance(tile center, segment) vs 2t + RMAX
        float dx  = cx - vx;
        float dy  = cy - vy;
        float dot = dx * ex + dy * ey;
        float fr  = __saturatef(dot * invd2);
        float ddx = fmaf(-fr, ex, dx);
        float ddy = fmaf(-fr, ey, dy);
        float dq  = ddx * ddx + ddy * ddy;
        float thr = 2.0f * t + RMAX;
        if (dq <= thr * thr) {
            int p = atomicAdd(&s_n, 1);
            s_a[p] = make_float4(vx, vy, ex, ey);
            s_b[p] = make_float2(invd2, 1.0f / (4.0f * t * t));
        }
    }
    __syncthreads();

    const int n = s_n;
    const float px = (float)(ti + threadIdx.y);
    const float py = (float)(tj + threadIdx.x);

    float m = 1e30f;
    #pragma unroll 2
    for (int q = 0; q < n; q++) {
        float4 a = s_a[q];
        float2 b = s_b[q];
        float dx  = px - a.x;
        float dy  = py - a.y;
        float dot = dx * a.z + dy * a.w;
        float fr  = __saturatef(dot * b.x);
        float ddx = fmaf(-fr, a.z, dx);
        float ddy = fmaf(-fr, a.w, dy);
        float dq  = fmaf(ddx, ddx, ddy * ddy);
        m = fminf(m, dq * b.y);
    }

    out[(ti + threadIdx.y) * G + (tj + threadIdx.x)] = fminf(sqrtf(m), 1.0f);
}

extern "C" void kernel_launch(void* const* d_in, const int* in_sizes, int n_in,
                              void* d_out, int out_size) {
    // metadata order: strokes [32,8,2] f32 (512 elems), thicknesses [32] f32.
    const float* strokes = (const float*)d_in[0];
    const float* thick   = (const float*)d_in[1];
    if (n_in >= 2 && in_sizes[0] == S && in_sizes[1] == S * PTS * 2) {
        // defensive: swapped metadata order
        strokes = (const float*)d_in[1];
        thick   = (const float*)d_in[0];
    }
    float* out = (float*)d_out;

    dim3 block(TILE, TILE);
    dim3 grid(G / TILE, G / TILE);
    render_kernel<<<grid, block>>>(strokes, thick, out);
}